// round 1
// baseline (speedup 1.0000x reference)
#include <cuda_runtime.h>
#include <math.h>

#define HH   192
#define WW   192
#define CIN  64
#define SHC  8
#define NB   8
#define NPIX (HH*WW)

// scratch for h = gelu(conv1(x)) : 8 batches x 8 channels x 192 x 192 fp32 (9.4 MB)
__device__ float g_h[(size_t)NB * SHC * NPIX];

__device__ __forceinline__ void cp_async4(void* dst, const void* src) {
    unsigned s = (unsigned)__cvta_generic_to_shared(dst);
    asm volatile("cp.async.ca.shared.global [%0], [%1], 4;\n" :: "r"(s), "l"(src));
}

// ---------------------------------------------------------------------------
// Kernel 1: 3x3 SAME conv (64 -> 8) + exact GELU.
// Block: 256 threads, tile 64(w) x 32(h). Thread: 8 oc x 8 px along x.
// Weights in smem (broadcast LDS), input tile double-buffered via cp.async.
// ---------------------------------------------------------------------------
__global__ void __launch_bounds__(256, 1)
conv1_gelu_kernel(const float* __restrict__ x, const float* __restrict__ w1)
{
    __shared__ float wsm[CIN * 9 * SHC];     // [ic][tap][oc]
    __shared__ float dsm[2][34 * 68];        // 34 rows x 66 cols (stride 68), double buffered

    const int tid   = threadIdx.x;
    const int b     = blockIdx.z;
    const int tileX = blockIdx.x * 64;
    const int tileY = blockIdx.y * 32;

    // stage weights: w1[oc][ic][ky][kx] -> wsm[ic*72 + tap*8 + oc]
    for (int i = tid; i < CIN * 9 * SHC; i += 256) {
        int oc  = i & 7;
        int tap = (i >> 3) % 9;
        int ic  = i / 72;
        wsm[i] = w1[(oc * CIN + ic) * 9 + tap];
    }

    const float* xb = x + (size_t)b * CIN * NPIX;

    auto load_tile = [&](int ic, int buf) {
        const float* src = xb + (size_t)ic * NPIX;
        for (int i = tid; i < 34 * 66; i += 256) {
            int r    = i / 66;
            int ccol = i - r * 66;
            int gy   = tileY - 1 + r;
            int gx   = tileX - 1 + ccol;
            float* dp = &dsm[buf][r * 68 + ccol];
            if ((unsigned)gy < (unsigned)HH && (unsigned)gx < (unsigned)WW)
                cp_async4(dp, src + gy * WW + gx);
            else
                *dp = 0.f;                    // SAME zero padding
        }
    };

    load_tile(0, 0);
    asm volatile("cp.async.commit_group;\n");

    const int tx = (tid & 7) * 8;   // 8 threads cover 64 px
    const int ty = tid >> 3;        // 32 rows

    float acc[8][8];
    #pragma unroll
    for (int oc = 0; oc < 8; oc++)
        #pragma unroll
        for (int p = 0; p < 8; p++) acc[oc][p] = 0.f;

    for (int ic = 0; ic < CIN; ic++) {
        __syncthreads();   // previous compute finished reading buffer we reload next
        if (ic + 1 < CIN) {
            load_tile(ic + 1, (ic + 1) & 1);
            asm volatile("cp.async.commit_group;\n");
            asm volatile("cp.async.wait_group 1;\n");
        } else {
            asm volatile("cp.async.wait_group 0;\n");
        }
        __syncthreads();   // current buffer fully visible

        const float* dd = &dsm[ic & 1][ty * 68 + tx];
        float rw[3][10];
        #pragma unroll
        for (int q = 0; q < 10; q++) {
            rw[0][q] = dd[q];
            rw[1][q] = dd[68 + q];
            rw[2][q] = dd[136 + q];
        }
        const float* wp = &wsm[ic * 72];
        #pragma unroll
        for (int ky = 0; ky < 3; ky++)
            #pragma unroll
            for (int kx = 0; kx < 3; kx++)
                #pragma unroll
                for (int oc = 0; oc < 8; oc++) {
                    float wv = wp[(ky * 3 + kx) * 8 + oc];
                    #pragma unroll
                    for (int p = 0; p < 8; p++)
                        acc[oc][p] = fmaf(rw[ky][p + kx], wv, acc[oc][p]);
                }
    }

    const int gy  = tileY + ty;
    const int gx0 = tileX + tx;
    const float inv_sqrt2 = 0.70710678118654752f;
    #pragma unroll
    for (int oc = 0; oc < 8; oc++) {
        float* hp = &g_h[(((size_t)b * SHC + oc) * HH + gy) * WW + gx0];
        #pragma unroll
        for (int half = 0; half < 2; half++) {
            float4 o;
            float v;
            v = acc[oc][half * 4 + 0]; o.x = 0.5f * v * (1.f + erff(v * inv_sqrt2));
            v = acc[oc][half * 4 + 1]; o.y = 0.5f * v * (1.f + erff(v * inv_sqrt2));
            v = acc[oc][half * 4 + 2]; o.z = 0.5f * v * (1.f + erff(v * inv_sqrt2));
            v = acc[oc][half * 4 + 3]; o.w = 0.5f * v * (1.f + erff(v * inv_sqrt2));
            reinterpret_cast<float4*>(hp)[half] = o;
        }
    }
}

// ---------------------------------------------------------------------------
// Kernel 2: per-(b,c) block. Whole 192x192 image of x[b,c] in smem -> all
// bilinear gathers are LDS. 1x1 conv coefficients computed on the fly from h.
// ---------------------------------------------------------------------------
__device__ __forceinline__ float bilin(const float* __restrict__ img, float px, float py)
{
    px = fminf(fmaxf(px, 0.f), 191.f);
    py = fminf(fmaxf(py, 0.f), 191.f);
    float x0f = floorf(px), y0f = floorf(py);
    float wx = px - x0f, wy = py - y0f;
    int x0 = (int)x0f, y0 = (int)y0f;
    int x1 = min(x0 + 1, 191);
    int y1 = min(y0 + 1, 191);
    const float* r0 = img + y0 * WW;
    const float* r1 = img + y1 * WW;
    float v00 = r0[x0], v01 = r0[x1];
    float v10 = r1[x0], v11 = r1[x1];
    // v00*(1-wx)+v01*wx  (fma form; differs from ref by ~1 ulp)
    float top = fmaf(v01 - v00, wx, v00);
    float bot = fmaf(v11 - v10, wx, v10);
    return fmaf(bot - top, wy, top);
}

__device__ __forceinline__ float to_px(float gplus)  // ((g)+1)*0.5*191, ref op order
{
    return ((gplus + 1.0f) * 0.5f) * 191.0f;
}

__global__ void __launch_bounds__(512, 1)
fuse_kernel(const float* __restrict__ x, const float* __restrict__ w2,
            const float* __restrict__ b2, const float* __restrict__ lsc,
            float* __restrict__ out)
{
    extern __shared__ float img[];           // 192*192 floats = 147456 B
    const int bc = blockIdx.x;
    const int b  = bc >> 6;
    const int c  = bc & 63;

    // stage full x[b,c] image
    const float4* src  = reinterpret_cast<const float4*>(x + (size_t)bc * NPIX);
    float4*       dst4 = reinterpret_cast<float4*>(img);
    for (int i = threadIdx.x; i < NPIX / 4; i += blockDim.x) dst4[i] = src[i];

    // hoist the 4x8 weight rows + biases for this channel
    float wreg[4][8], breg[4];
    #pragma unroll
    for (int j = 0; j < 4; j++) {
        breg[j] = __ldg(&b2[4 * c + j]);
        #pragma unroll
        for (int s = 0; s < 8; s++) wreg[j][s] = __ldg(&w2[(4 * c + j) * 8 + s]);
    }
    const float esc = expf(__ldg(lsc));
    const float* hb = g_h + (size_t)b * SHC * NPIX;
    float* ob = out + (size_t)bc * NPIX;

    const float step = 2.0f / 191.0f;

    __syncthreads();

    for (int idx = threadIdx.x; idx < NPIX; idx += blockDim.x) {
        int yi = idx / WW;
        int xi = idx - yi * WW;

        float hv[8];
        #pragma unroll
        for (int s = 0; s < 8; s++) hv[s] = __ldg(&hb[s * NPIX + idx]);

        float a  = breg[0], bx = breg[1], by = breg[2], cv = breg[3];
        #pragma unroll
        for (int s = 0; s < 8; s++) {
            a  = fmaf(hv[s], wreg[0][s], a);
            bx = fmaf(hv[s], wreg[1][s], bx);
            by = fmaf(hv[s], wreg[2][s], by);
            cv = fmaf(hv[s], wreg[3][s], cv);
        }

        // softplus (stable, = jnp.logaddexp(a, 0))
        float sp = fmaxf(a, 0.f) + log1pf(expf(-fabsf(a)));
        float s  = sqrtf(sp * 0.1f + 1e-8f);
        float dx = bx * 0.1f;
        float dy = by * 0.1f;
        cv = fminf(fmaxf(cv, -5.f), 5.f);

        // normalized grid coords, reference op order
        float gxv = fmaf((float)xi, step, -1.0f);
        float gyv = fmaf((float)yi, step, -1.0f);

        float gx_pdx = (gxv + dx);            // bgx + dx
        float gy_pdy = (gyv + dy);            // bgy + dy
        float px1 = to_px((gxv + s) + dx);    // bgx + s + dx
        float px2 = to_px((gxv - s) + dx);    // bgx - s + dx
        float px3 = to_px(gx_pdx);
        float py12 = to_px(gy_pdy);
        float py3 = to_px((gyv + s) + dy);    // bgy + s + dy
        float py4 = to_px((gyv - s) + dy);    // bgy - s + dy

        float u1 = bilin(img, px1, py12);
        float u2 = bilin(img, px2, py12);
        float u3 = bilin(img, px3, py3);
        float u4 = bilin(img, px3, py4);

        float evo = 0.25f * (((u1 + u2) + u3) + u4);
        float xv  = img[idx];
        ob[idx] = esc * (evo + (0.1f * cv) * xv);
    }
}

// ---------------------------------------------------------------------------
extern "C" void kernel_launch(void* const* d_in, const int* in_sizes, int n_in,
                              void* d_out, int out_size)
{
    const float *x = nullptr, *w1 = nullptr, *w2 = nullptr, *b2 = nullptr, *ls = nullptr;
    for (int i = 0; i < n_in; i++) {
        switch (in_sizes[i]) {
            case NB * CIN * NPIX: x  = (const float*)d_in[i]; break;  // 18874368
            case SHC * CIN * 9:   w1 = (const float*)d_in[i]; break;  // 4608
            case 4 * CIN * SHC:   w2 = (const float*)d_in[i]; break;  // 2048
            case 4 * CIN:         b2 = (const float*)d_in[i]; break;  // 256
            case 1:               ls = (const float*)d_in[i]; break;
            default: break;
        }
    }

    dim3 g1(3, 6, NB);                       // 64x32 tiles
    conv1_gelu_kernel<<<g1, 256>>>(x, w1);

    const int smem = NPIX * (int)sizeof(float);  // 147456
    cudaFuncSetAttribute(fuse_kernel, cudaFuncAttributeMaxDynamicSharedMemorySize, smem);
    fuse_kernel<<<NB * CIN, 512, smem>>>(x, w2, b2, ls, (float*)d_out);
}

// round 2
// speedup vs baseline: 1.2500x; 1.2500x over previous
#include <cuda_runtime.h>
#include <math.h>

#define HH   192
#define WW   192
#define CIN  64
#define SHC  8
#define NB   8
#define NPIX (HH*WW)

// scratch for h = gelu(conv1(x)) : 8 batches x 8 channels x 192 x 192 fp32 (9.4 MB)
__device__ float g_h[(size_t)NB * SHC * NPIX];

__device__ __forceinline__ void cp_async4(void* dst, const void* src) {
    unsigned s = (unsigned)__cvta_generic_to_shared(dst);
    asm volatile("cp.async.ca.shared.global [%0], [%1], 4;\n" :: "r"(s), "l"(src));
}

__device__ __forceinline__ float fsqrt_approx(float v) {
    float r;
    asm("sqrt.approx.f32 %0, %1;" : "=f"(r) : "f"(v));
    return r;
}

// ---------------------------------------------------------------------------
// Kernel 1: 3x3 SAME conv (64 -> 8) + exact GELU.  (unchanged, ~77us, FMA-bound)
// Block: 256 threads, tile 64(w) x 32(h). Thread: 8 oc x 8 px along x.
// ---------------------------------------------------------------------------
__global__ void __launch_bounds__(256, 1)
conv1_gelu_kernel(const float* __restrict__ x, const float* __restrict__ w1)
{
    __shared__ float wsm[CIN * 9 * SHC];     // [ic][tap][oc]
    __shared__ float dsm[2][34 * 68];        // 34 rows x 66 cols (stride 68), double buffered

    const int tid   = threadIdx.x;
    const int b     = blockIdx.z;
    const int tileX = blockIdx.x * 64;
    const int tileY = blockIdx.y * 32;

    for (int i = tid; i < CIN * 9 * SHC; i += 256) {
        int oc  = i & 7;
        int tap = (i >> 3) % 9;
        int ic  = i / 72;
        wsm[i] = w1[(oc * CIN + ic) * 9 + tap];
    }

    const float* xb = x + (size_t)b * CIN * NPIX;

    auto load_tile = [&](int ic, int buf) {
        const float* src = xb + (size_t)ic * NPIX;
        for (int i = tid; i < 34 * 66; i += 256) {
            int r    = i / 66;
            int ccol = i - r * 66;
            int gy   = tileY - 1 + r;
            int gx   = tileX - 1 + ccol;
            float* dp = &dsm[buf][r * 68 + ccol];
            if ((unsigned)gy < (unsigned)HH && (unsigned)gx < (unsigned)WW)
                cp_async4(dp, src + gy * WW + gx);
            else
                *dp = 0.f;
        }
    };

    load_tile(0, 0);
    asm volatile("cp.async.commit_group;\n");

    const int tx = (tid & 7) * 8;
    const int ty = tid >> 3;

    float acc[8][8];
    #pragma unroll
    for (int oc = 0; oc < 8; oc++)
        #pragma unroll
        for (int p = 0; p < 8; p++) acc[oc][p] = 0.f;

    for (int ic = 0; ic < CIN; ic++) {
        __syncthreads();
        if (ic + 1 < CIN) {
            load_tile(ic + 1, (ic + 1) & 1);
            asm volatile("cp.async.commit_group;\n");
            asm volatile("cp.async.wait_group 1;\n");
        } else {
            asm volatile("cp.async.wait_group 0;\n");
        }
        __syncthreads();

        const float* dd = &dsm[ic & 1][ty * 68 + tx];
        float rw[3][10];
        #pragma unroll
        for (int q = 0; q < 10; q++) {
            rw[0][q] = dd[q];
            rw[1][q] = dd[68 + q];
            rw[2][q] = dd[136 + q];
        }
        const float* wp = &wsm[ic * 72];
        #pragma unroll
        for (int ky = 0; ky < 3; ky++)
            #pragma unroll
            for (int kx = 0; kx < 3; kx++)
                #pragma unroll
                for (int oc = 0; oc < 8; oc++) {
                    float wv = wp[(ky * 3 + kx) * 8 + oc];
                    #pragma unroll
                    for (int p = 0; p < 8; p++)
                        acc[oc][p] = fmaf(rw[ky][p + kx], wv, acc[oc][p]);
                }
    }

    const int gy  = tileY + ty;
    const int gx0 = tileX + tx;
    const float inv_sqrt2 = 0.70710678118654752f;
    #pragma unroll
    for (int oc = 0; oc < 8; oc++) {
        float* hp = &g_h[(((size_t)b * SHC + oc) * HH + gy) * WW + gx0];
        #pragma unroll
        for (int half = 0; half < 2; half++) {
            float4 o;
            float v;
            v = acc[oc][half * 4 + 0]; o.x = 0.5f * v * (1.f + erff(v * inv_sqrt2));
            v = acc[oc][half * 4 + 1]; o.y = 0.5f * v * (1.f + erff(v * inv_sqrt2));
            v = acc[oc][half * 4 + 2]; o.z = 0.5f * v * (1.f + erff(v * inv_sqrt2));
            v = acc[oc][half * 4 + 3]; o.w = 0.5f * v * (1.f + erff(v * inv_sqrt2));
            reinterpret_cast<float4*>(hp)[half] = o;
        }
    }
}

// ---------------------------------------------------------------------------
// Kernel 2: 2 blocks per (b,c), each block owns 96 output rows but stages the
// full 192x192 image (+1 padded row) in smem so every bilinear tap is an LDS.
// Instruction-diet version: fast transcendentals, no per-pixel div, shared
// tap setup, fused pixel-coordinate FMA, padded image kills the +1 clamps.
// ---------------------------------------------------------------------------
#define PAD 200

__global__ void __launch_bounds__(768, 1)
fuse_kernel(const float* __restrict__ x, const float* __restrict__ w2,
            const float* __restrict__ b2, const float* __restrict__ lsc,
            float* __restrict__ out)
{
    extern __shared__ float img[];           // NPIX + PAD floats
    const int bc   = blockIdx.x >> 1;
    const int half = blockIdx.x & 1;
    const int c    = bc & 63;

    // stage full x[b,c] image (vectorized) + zero pad row
    const float4* src  = reinterpret_cast<const float4*>(x + (size_t)bc * NPIX);
    float4*       dst4 = reinterpret_cast<float4*>(img);
    for (int i = threadIdx.x; i < NPIX / 4; i += 768) dst4[i] = src[i];
    if (threadIdx.x < PAD / 4)
        reinterpret_cast<float4*>(img + NPIX)[threadIdx.x] = make_float4(0.f, 0.f, 0.f, 0.f);

    // hoist per-channel weights + biases
    float wreg[4][8], breg[4];
    #pragma unroll
    for (int j = 0; j < 4; j++) {
        breg[j] = __ldg(&b2[4 * c + j]);
        #pragma unroll
        for (int s = 0; s < 8; s++) wreg[j][s] = __ldg(&w2[(4 * c + j) * 8 + s]);
    }
    const float esc = expf(__ldg(lsc));
    const float* hb = g_h + (size_t)(bc >> 6) * SHC * NPIX;
    float* ob = out + (size_t)bc * NPIX;

    const float step = 2.0f / 191.0f;

    // thread -> fixed column + row phase (no per-pixel div/mod)
    const int rphase = threadIdx.x / 192;            // 0..3
    const int xi     = threadIdx.x - rphase * 192;   // 0..191
    const float gxv  = fmaf((float)xi, step, -1.0f);
    const int ybase  = half * 96;

    __syncthreads();

    for (int yi = ybase + rphase; yi < ybase + 96; yi += 4) {
        const int   idx = yi * WW + xi;
        const float gyv = fmaf((float)yi, step, -1.0f);

        const float* hp = hb + idx;
        float hv[8];
        #pragma unroll
        for (int s = 0; s < 8; s++) hv[s] = __ldg(hp + s * NPIX);

        float a  = breg[0], bx = breg[1], by = breg[2], cv = breg[3];
        #pragma unroll
        for (int s = 0; s < 8; s++) {
            a  = fmaf(hv[s], wreg[0][s], a);
            bx = fmaf(hv[s], wreg[1][s], bx);
            by = fmaf(hv[s], wreg[2][s], by);
            cv = fmaf(hv[s], wreg[3][s], cv);
        }

        // softplus (stable) with MUFU transcendentals
        float t  = __expf(-fabsf(a));
        float sp = fmaxf(a, 0.f) + __logf(1.0f + t);
        float s  = fsqrt_approx(fmaf(sp, 0.1f, 1e-8f));
        float dx = bx * 0.1f;
        float dy = by * 0.1f;
        cv = fminf(fmaxf(cv, -5.f), 5.f);

        // pixel coords: px = ((g+1)*0.5)*191  ==  g*95.5 + 95.5
        float px1  = fmaf((gxv + s) + dx, 95.5f, 95.5f);
        float px2  = fmaf((gxv - s) + dx, 95.5f, 95.5f);
        float px3  = fmaf( gxv + dx,      95.5f, 95.5f);
        float py12 = fmaf( gyv + dy,      95.5f, 95.5f);
        float py3  = fmaf((gyv + s) + dy, 95.5f, 95.5f);
        float py4  = fmaf((gyv - s) + dy, 95.5f, 95.5f);

        // ---- u1,u2: shared y-row setup ----
        float pyc = fminf(fmaxf(py12, 0.f), 191.f);
        float y0f = floorf(pyc);
        float wy  = pyc - y0f;

        float pxc1 = fminf(fmaxf(px1, 0.f), 191.f);
        float x0f1 = floorf(pxc1);
        float wx1  = pxc1 - x0f1;
        int   o1   = (int)fmaf(y0f, 192.f, x0f1);
        float v00 = img[o1],       v01 = img[o1 + 1];
        float v10 = img[o1 + 192], v11 = img[o1 + 193];
        float top = fmaf(v01 - v00, wx1, v00);
        float bot = fmaf(v11 - v10, wx1, v10);
        float u1  = fmaf(bot - top, wy, top);

        float pxc2 = fminf(fmaxf(px2, 0.f), 191.f);
        float x0f2 = floorf(pxc2);
        float wx2  = pxc2 - x0f2;
        int   o2   = (int)fmaf(y0f, 192.f, x0f2);
        v00 = img[o2];       v01 = img[o2 + 1];
        v10 = img[o2 + 192]; v11 = img[o2 + 193];
        top = fmaf(v01 - v00, wx2, v00);
        bot = fmaf(v11 - v10, wx2, v10);
        float u2 = fmaf(bot - top, wy, top);

        // ---- u3,u4: shared x-column setup ----
        float pxc3 = fminf(fmaxf(px3, 0.f), 191.f);
        float x0f3 = floorf(pxc3);
        float wx3  = pxc3 - x0f3;

        float pyc3 = fminf(fmaxf(py3, 0.f), 191.f);
        float y0f3 = floorf(pyc3);
        float wy3  = pyc3 - y0f3;
        int   o3   = (int)fmaf(y0f3, 192.f, x0f3);
        v00 = img[o3];       v01 = img[o3 + 1];
        v10 = img[o3 + 192]; v11 = img[o3 + 193];
        top = fmaf(v01 - v00, wx3, v00);
        bot = fmaf(v11 - v10, wx3, v10);
        float u3 = fmaf(bot - top, wy3, top);

        float pyc4 = fminf(fmaxf(py4, 0.f), 191.f);
        float y0f4 = floorf(pyc4);
        float wy4  = pyc4 - y0f4;
        int   o4   = (int)fmaf(y0f4, 192.f, x0f3);
        v00 = img[o4];       v01 = img[o4 + 1];
        v10 = img[o4 + 192]; v11 = img[o4 + 193];
        top = fmaf(v01 - v00, wx3, v00);
        bot = fmaf(v11 - v10, wx3, v10);
        float u4 = fmaf(bot - top, wy4, top);

        float evo = 0.25f * (((u1 + u2) + u3) + u4);
        float xv  = img[idx];
        ob[idx] = esc * (evo + (0.1f * cv) * xv);
    }
}

// ---------------------------------------------------------------------------
extern "C" void kernel_launch(void* const* d_in, const int* in_sizes, int n_in,
                              void* d_out, int out_size)
{
    const float *x = nullptr, *w1 = nullptr, *w2 = nullptr, *b2 = nullptr, *ls = nullptr;
    for (int i = 0; i < n_in; i++) {
        switch (in_sizes[i]) {
            case NB * CIN * NPIX: x  = (const float*)d_in[i]; break;  // 18874368
            case SHC * CIN * 9:   w1 = (const float*)d_in[i]; break;  // 4608
            case 4 * CIN * SHC:   w2 = (const float*)d_in[i]; break;  // 2048
            case 4 * CIN:         b2 = (const float*)d_in[i]; break;  // 256
            case 1:               ls = (const float*)d_in[i]; break;
            default: break;
        }
    }

    dim3 g1(3, 6, NB);                       // 64x32 tiles
    conv1_gelu_kernel<<<g1, 256>>>(x, w1);

    const int smem = (NPIX + PAD) * (int)sizeof(float);  // 148256
    cudaFuncSetAttribute(fuse_kernel, cudaFuncAttributeMaxDynamicSharedMemorySize, smem);
    fuse_kernel<<<NB * CIN * 2, 768, smem>>>(x, w2, b2, ls, (float*)d_out);
}

// round 3
// speedup vs baseline: 1.3162x; 1.0530x over previous
#include <cuda_runtime.h>
#include <math.h>

#define HH   192
#define WW   192
#define CIN  64
#define SHC  8
#define NB   8
#define NPIX (HH*WW)

typedef unsigned long long ull;

// scratch for h = gelu(conv1(x)), PIXEL-MAJOR: [b][pix][8 sh-channels] (9.4 MB)
__device__ float g_h[(size_t)NB * NPIX * SHC];

__device__ __forceinline__ void cp_async4(void* dst, const void* src) {
    unsigned s = (unsigned)__cvta_generic_to_shared(dst);
    asm volatile("cp.async.ca.shared.global [%0], [%1], 4;\n" :: "r"(s), "l"(src));
}
__device__ __forceinline__ float fsqrt_approx(float v) {
    float r; asm("sqrt.approx.f32 %0, %1;" : "=f"(r) : "f"(v)); return r;
}
// ---- f32x2 packed helpers (bit-exact: two IEEE fp32 fmas per instruction) ----
__device__ __forceinline__ ull ffma2(ull a, ull b, ull c) {
    ull r; asm("fma.rn.f32x2 %0, %1, %2, %3;" : "=l"(r) : "l"(a), "l"(b), "l"(c)); return r;
}
__device__ __forceinline__ ull dup2(float v) {
    ull r; asm("mov.b64 %0, {%1, %1};" : "=l"(r) : "f"(v)); return r;
}
__device__ __forceinline__ ull pack2(float lo, float hi) {
    ull r; asm("mov.b64 %0, {%1, %2};" : "=l"(r) : "f"(lo), "f"(hi)); return r;
}
__device__ __forceinline__ void unpack2(ull v, float& lo, float& hi) {
    asm("mov.b64 {%0, %1}, %2;" : "=f"(lo), "=f"(hi) : "l"(v));
}

// ---------------------------------------------------------------------------
// Kernel 1: 3x3 SAME conv (64 -> 8) + exact GELU, f32x2-packed across oc pairs.
// Block: 256 threads, tile 64(w) x 32(h). Thread: 4 oc-pairs x 8 px.
// Writes h pixel-major so kernel 2 reads 2x LDG.128 per pixel.
// ---------------------------------------------------------------------------
__global__ void __launch_bounds__(256, 1)
conv1_gelu_kernel(const float* __restrict__ x, const float* __restrict__ w1)
{
    __shared__ float wsm[CIN * 9 * SHC];     // [ic][tap][oc]  (oc-pairs 8B aligned)
    __shared__ float dsm[2][34 * 68];        // double buffered input tile

    const int tid   = threadIdx.x;
    const int b     = blockIdx.z;
    const int tileX = blockIdx.x * 64;
    const int tileY = blockIdx.y * 32;

    for (int i = tid; i < CIN * 9 * SHC; i += 256) {
        int oc  = i & 7;
        int tap = (i >> 3) % 9;
        int ic  = i / 72;
        wsm[i] = w1[(oc * CIN + ic) * 9 + tap];
    }

    const float* xb = x + (size_t)b * CIN * NPIX;

    auto load_tile = [&](int ic, int buf) {
        const float* src = xb + (size_t)ic * NPIX;
        for (int i = tid; i < 34 * 66; i += 256) {
            int r    = i / 66;
            int ccol = i - r * 66;
            int gy   = tileY - 1 + r;
            int gx   = tileX - 1 + ccol;
            float* dp = &dsm[buf][r * 68 + ccol];
            if ((unsigned)gy < (unsigned)HH && (unsigned)gx < (unsigned)WW)
                cp_async4(dp, src + gy * WW + gx);
            else
                *dp = 0.f;
        }
    };

    load_tile(0, 0);
    asm volatile("cp.async.commit_group;\n");

    const int tx = (tid & 7) * 8;
    const int ty = tid >> 3;

    ull acc2[4][8];                          // [oc-pair][px]
    #pragma unroll
    for (int q = 0; q < 4; q++)
        #pragma unroll
        for (int p = 0; p < 8; p++) acc2[q][p] = 0ull;

    for (int ic = 0; ic < CIN; ic++) {
        __syncthreads();
        if (ic + 1 < CIN) {
            load_tile(ic + 1, (ic + 1) & 1);
            asm volatile("cp.async.commit_group;\n");
            asm volatile("cp.async.wait_group 1;\n");
        } else {
            asm volatile("cp.async.wait_group 0;\n");
        }
        __syncthreads();

        const float* dd = &dsm[ic & 1][ty * 68 + tx];
        float rw[3][10];
        #pragma unroll
        for (int q = 0; q < 10; q++) {
            rw[0][q] = dd[q];
            rw[1][q] = dd[68 + q];
            rw[2][q] = dd[136 + q];
        }
        const float* wp = &wsm[ic * 72];
        #pragma unroll
        for (int t = 0; t < 9; t++) {
            const int ky = t / 3, kx = t % 3;
            const ull* wq = reinterpret_cast<const ull*>(wp + t * 8);
            ull w0 = wq[0], w1q = wq[1], w2q = wq[2], w3q = wq[3];   // LDS.64 oc-pairs
            #pragma unroll
            for (int p = 0; p < 8; p++) {
                ull d = dup2(rw[ky][p + kx]);
                acc2[0][p] = ffma2(d, w0,  acc2[0][p]);
                acc2[1][p] = ffma2(d, w1q, acc2[1][p]);
                acc2[2][p] = ffma2(d, w2q, acc2[2][p]);
                acc2[3][p] = ffma2(d, w3q, acc2[3][p]);
            }
        }
    }

    const int gy  = tileY + ty;
    const int gx0 = tileX + tx;
    const float inv_sqrt2 = 0.70710678118654752f;
    float* hbase = g_h + ((size_t)b * NPIX + (size_t)gy * WW + gx0) * SHC;
    #pragma unroll
    for (int p = 0; p < 8; p++) {
        float v[8];
        unpack2(acc2[0][p], v[0], v[1]);
        unpack2(acc2[1][p], v[2], v[3]);
        unpack2(acc2[2][p], v[4], v[5]);
        unpack2(acc2[3][p], v[6], v[7]);
        float4 o0, o1;
        float u;
        u = v[0]; o0.x = 0.5f * u * (1.f + erff(u * inv_sqrt2));
        u = v[1]; o0.y = 0.5f * u * (1.f + erff(u * inv_sqrt2));
        u = v[2]; o0.z = 0.5f * u * (1.f + erff(u * inv_sqrt2));
        u = v[3]; o0.w = 0.5f * u * (1.f + erff(u * inv_sqrt2));
        u = v[4]; o1.x = 0.5f * u * (1.f + erff(u * inv_sqrt2));
        u = v[5]; o1.y = 0.5f * u * (1.f + erff(u * inv_sqrt2));
        u = v[6]; o1.z = 0.5f * u * (1.f + erff(u * inv_sqrt2));
        u = v[7]; o1.w = 0.5f * u * (1.f + erff(u * inv_sqrt2));
        float4* hp = reinterpret_cast<float4*>(hbase + (size_t)p * SHC);
        hp[0] = o0;
        hp[1] = o1;
    }
}

// ---------------------------------------------------------------------------
// Kernel 2: 2 blocks per (b,c); full padded image in smem (all taps are LDS).
// h read as 2x LDG.128/pixel; coeff dot-products f32x2-packed.
// ---------------------------------------------------------------------------
#define PAD 200

__global__ void __launch_bounds__(768, 1)
fuse_kernel(const float* __restrict__ x, const float* __restrict__ w2,
            const float* __restrict__ b2, const float* __restrict__ lsc,
            float* __restrict__ out)
{
    extern __shared__ float img[];           // NPIX + PAD floats
    const int bc   = blockIdx.x >> 1;
    const int half = blockIdx.x & 1;
    const int c    = bc & 63;

    const float4* src  = reinterpret_cast<const float4*>(x + (size_t)bc * NPIX);
    float4*       dst4 = reinterpret_cast<float4*>(img);
    for (int i = threadIdx.x; i < NPIX / 4; i += 768) dst4[i] = src[i];
    if (threadIdx.x < PAD / 4)
        reinterpret_cast<float4*>(img + NPIX)[threadIdx.x] = make_float4(0.f, 0.f, 0.f, 0.f);

    // packed per-channel weights: w01[s] = (w_a[s], w_bx[s]), w23[s] = (w_by[s], w_c[s])
    ull w01[8], w23[8];
    #pragma unroll
    for (int s = 0; s < 8; s++) {
        w01[s] = pack2(__ldg(&w2[(4 * c + 0) * 8 + s]), __ldg(&w2[(4 * c + 1) * 8 + s]));
        w23[s] = pack2(__ldg(&w2[(4 * c + 2) * 8 + s]), __ldg(&w2[(4 * c + 3) * 8 + s]));
    }
    const ull bias01 = pack2(__ldg(&b2[4 * c + 0]), __ldg(&b2[4 * c + 1]));
    const ull bias23 = pack2(__ldg(&b2[4 * c + 2]), __ldg(&b2[4 * c + 3]));

    const float esc = expf(__ldg(lsc));
    const float* hb = g_h + (size_t)(bc >> 6) * NPIX * SHC;
    float* ob = out + (size_t)bc * NPIX;

    const float step = 2.0f / 191.0f;

    const int rphase = threadIdx.x / 192;            // 0..3
    const int xi     = threadIdx.x - rphase * 192;   // 0..191
    const float gxv  = fmaf((float)xi, step, -1.0f);
    const int ybase  = half * 96;

    __syncthreads();

    for (int yi = ybase + rphase; yi < ybase + 96; yi += 4) {
        const int   idx = yi * WW + xi;
        const float gyv = fmaf((float)yi, step, -1.0f);

        const float4* hp = reinterpret_cast<const float4*>(hb + (size_t)idx * SHC);
        float4 h0 = hp[0];
        float4 h1 = hp[1];

        ull a01 = bias01, a23 = bias23;
        {
            ull d;
            d = dup2(h0.x); a01 = ffma2(d, w01[0], a01); a23 = ffma2(d, w23[0], a23);
            d = dup2(h0.y); a01 = ffma2(d, w01[1], a01); a23 = ffma2(d, w23[1], a23);
            d = dup2(h0.z); a01 = ffma2(d, w01[2], a01); a23 = ffma2(d, w23[2], a23);
            d = dup2(h0.w); a01 = ffma2(d, w01[3], a01); a23 = ffma2(d, w23[3], a23);
            d = dup2(h1.x); a01 = ffma2(d, w01[4], a01); a23 = ffma2(d, w23[4], a23);
            d = dup2(h1.y); a01 = ffma2(d, w01[5], a01); a23 = ffma2(d, w23[5], a23);
            d = dup2(h1.z); a01 = ffma2(d, w01[6], a01); a23 = ffma2(d, w23[6], a23);
            d = dup2(h1.w); a01 = ffma2(d, w01[7], a01); a23 = ffma2(d, w23[7], a23);
        }
        float a, bx, by, cv;
        unpack2(a01, a, bx);
        unpack2(a23, by, cv);

        // softplus (stable) with MUFU transcendentals
        float t  = __expf(-fabsf(a));
        float sp = fmaxf(a, 0.f) + __logf(1.0f + t);
        float s  = fsqrt_approx(fmaf(sp, 0.1f, 1e-8f));
        float dx = bx * 0.1f;
        float dy = by * 0.1f;
        cv = fminf(fmaxf(cv, -5.f), 5.f);

        // pixel coords: px = ((g+1)*0.5)*191 == g*95.5 + 95.5
        float px1  = fmaf((gxv + s) + dx, 95.5f, 95.5f);
        float px2  = fmaf((gxv - s) + dx, 95.5f, 95.5f);
        float px3  = fmaf( gxv + dx,      95.5f, 95.5f);
        float py12 = fmaf( gyv + dy,      95.5f, 95.5f);
        float py3  = fmaf((gyv + s) + dy, 95.5f, 95.5f);
        float py4  = fmaf((gyv - s) + dy, 95.5f, 95.5f);

        // ---- u1,u2: shared y-row setup ----
        float pyc = fminf(fmaxf(py12, 0.f), 191.f);
        float y0f = floorf(pyc);
        float wy  = pyc - y0f;

        float pxc1 = fminf(fmaxf(px1, 0.f), 191.f);
        float x0f1 = floorf(pxc1);
        float wx1  = pxc1 - x0f1;
        int   o1   = (int)fmaf(y0f, 192.f, x0f1);
        float v00 = img[o1],       v01 = img[o1 + 1];
        float v10 = img[o1 + 192], v11 = img[o1 + 193];
        float top = fmaf(v01 - v00, wx1, v00);
        float bot = fmaf(v11 - v10, wx1, v10);
        float u1  = fmaf(bot - top, wy, top);

        float pxc2 = fminf(fmaxf(px2, 0.f), 191.f);
        float x0f2 = floorf(pxc2);
        float wx2  = pxc2 - x0f2;
        int   o2   = (int)fmaf(y0f, 192.f, x0f2);
        v00 = img[o2];       v01 = img[o2 + 1];
        v10 = img[o2 + 192]; v11 = img[o2 + 193];
        top = fmaf(v01 - v00, wx2, v00);
        bot = fmaf(v11 - v10, wx2, v10);
        float u2 = fmaf(bot - top, wy, top);

        // ---- u3,u4: shared x-column setup ----
        float pxc3 = fminf(fmaxf(px3, 0.f), 191.f);
        float x0f3 = floorf(pxc3);
        float wx3  = pxc3 - x0f3;

        float pyc3 = fminf(fmaxf(py3, 0.f), 191.f);
        float y0f3 = floorf(pyc3);
        float wy3  = pyc3 - y0f3;
        int   o3   = (int)fmaf(y0f3, 192.f, x0f3);
        v00 = img[o3];       v01 = img[o3 + 1];
        v10 = img[o3 + 192]; v11 = img[o3 + 193];
        top = fmaf(v01 - v00, wx3, v00);
        bot = fmaf(v11 - v10, wx3, v10);
        float u3 = fmaf(bot - top, wy3, top);

        float pyc4 = fminf(fmaxf(py4, 0.f), 191.f);
        float y0f4 = floorf(pyc4);
        float wy4  = pyc4 - y0f4;
        int   o4   = (int)fmaf(y0f4, 192.f, x0f3);
        v00 = img[o4];       v01 = img[o4 + 1];
        v10 = img[o4 + 192]; v11 = img[o4 + 193];
        top = fmaf(v01 - v00, wx3, v00);
        bot = fmaf(v11 - v10, wx3, v10);
        float u4 = fmaf(bot - top, wy4, top);

        float evo = 0.25f * (((u1 + u2) + u3) + u4);
        float xv  = img[idx];
        ob[idx] = esc * (evo + (0.1f * cv) * xv);
    }
}

// ---------------------------------------------------------------------------
extern "C" void kernel_launch(void* const* d_in, const int* in_sizes, int n_in,
                              void* d_out, int out_size)
{
    const float *x = nullptr, *w1 = nullptr, *w2 = nullptr, *b2 = nullptr, *ls = nullptr;
    for (int i = 0; i < n_in; i++) {
        switch (in_sizes[i]) {
            case NB * CIN * NPIX: x  = (const float*)d_in[i]; break;  // 18874368
            case SHC * CIN * 9:   w1 = (const float*)d_in[i]; break;  // 4608
            case 4 * CIN * SHC:   w2 = (const float*)d_in[i]; break;  // 2048
            case 4 * CIN:         b2 = (const float*)d_in[i]; break;  // 256
            case 1:               ls = (const float*)d_in[i]; break;
            default: break;
        }
    }

    dim3 g1(3, 6, NB);                       // 64x32 tiles
    conv1_gelu_kernel<<<g1, 256>>>(x, w1);

    const int smem = (NPIX + PAD) * (int)sizeof(float);  // 148256
    cudaFuncSetAttribute(fuse_kernel, cudaFuncAttributeMaxDynamicSharedMemorySize, smem);
    fuse_kernel<<<NB * CIN * 2, 768, smem>>>(x, w2, b2, ls, (float*)d_out);
}

// round 4
// speedup vs baseline: 1.4371x; 1.0918x over previous
#include <cuda_runtime.h>
#include <math.h>

#define HH   192
#define WW   192
#define CIN  64
#define SHC  8
#define NB   8
#define NPIX (HH*WW)

typedef unsigned long long ull;

// scratch for h = gelu(conv1(x)), PIXEL-MAJOR: [b][pix][8 sh-channels] (9.4 MB)
__device__ float g_h[(size_t)NB * NPIX * SHC];

__device__ __forceinline__ void cp_async4(void* dst, const void* src) {
    unsigned s = (unsigned)__cvta_generic_to_shared(dst);
    asm volatile("cp.async.ca.shared.global [%0], [%1], 4;\n" :: "r"(s), "l"(src));
}
__device__ __forceinline__ float fsqrt_approx(float v) {
    float r; asm("sqrt.approx.f32 %0, %1;" : "=f"(r) : "f"(v)); return r;
}
// ---- f32x2 packed helpers ----
__device__ __forceinline__ ull ffma2(ull a, ull b, ull c) {
    ull r; asm("fma.rn.f32x2 %0, %1, %2, %3;" : "=l"(r) : "l"(a), "l"(b), "l"(c)); return r;
}
__device__ __forceinline__ ull dup2(float v) {
    ull r; asm("mov.b64 %0, {%1, %1};" : "=l"(r) : "f"(v)); return r;
}
__device__ __forceinline__ ull pack2(float lo, float hi) {
    ull r; asm("mov.b64 %0, {%1, %2};" : "=l"(r) : "f"(lo), "f"(hi)); return r;
}
__device__ __forceinline__ void unpack2(ull v, float& lo, float& hi) {
    asm("mov.b64 {%0, %1}, %2;" : "=f"(lo), "=f"(hi) : "l"(v));
}

// ---------------------------------------------------------------------------
// Kernel 1: 3x3 SAME conv (64 -> 8) + exact GELU  (unchanged from R3; at the
// scalar/packed FFMA issue floor ~83us).
// ---------------------------------------------------------------------------
__global__ void __launch_bounds__(256, 1)
conv1_gelu_kernel(const float* __restrict__ x, const float* __restrict__ w1)
{
    __shared__ float wsm[CIN * 9 * SHC];     // [ic][tap][oc]
    __shared__ float dsm[2][34 * 68];        // double buffered input tile

    const int tid   = threadIdx.x;
    const int b     = blockIdx.z;
    const int tileX = blockIdx.x * 64;
    const int tileY = blockIdx.y * 32;

    for (int i = tid; i < CIN * 9 * SHC; i += 256) {
        int oc  = i & 7;
        int tap = (i >> 3) % 9;
        int ic  = i / 72;
        wsm[i] = w1[(oc * CIN + ic) * 9 + tap];
    }

    const float* xb = x + (size_t)b * CIN * NPIX;

    auto load_tile = [&](int ic, int buf) {
        const float* src = xb + (size_t)ic * NPIX;
        for (int i = tid; i < 34 * 66; i += 256) {
            int r    = i / 66;
            int ccol = i - r * 66;
            int gy   = tileY - 1 + r;
            int gx   = tileX - 1 + ccol;
            float* dp = &dsm[buf][r * 68 + ccol];
            if ((unsigned)gy < (unsigned)HH && (unsigned)gx < (unsigned)WW)
                cp_async4(dp, src + gy * WW + gx);
            else
                *dp = 0.f;
        }
    };

    load_tile(0, 0);
    asm volatile("cp.async.commit_group;\n");

    const int tx = (tid & 7) * 8;
    const int ty = tid >> 3;

    ull acc2[4][8];
    #pragma unroll
    for (int q = 0; q < 4; q++)
        #pragma unroll
        for (int p = 0; p < 8; p++) acc2[q][p] = 0ull;

    for (int ic = 0; ic < CIN; ic++) {
        __syncthreads();
        if (ic + 1 < CIN) {
            load_tile(ic + 1, (ic + 1) & 1);
            asm volatile("cp.async.commit_group;\n");
            asm volatile("cp.async.wait_group 1;\n");
        } else {
            asm volatile("cp.async.wait_group 0;\n");
        }
        __syncthreads();

        const float* dd = &dsm[ic & 1][ty * 68 + tx];
        float rw[3][10];
        #pragma unroll
        for (int q = 0; q < 10; q++) {
            rw[0][q] = dd[q];
            rw[1][q] = dd[68 + q];
            rw[2][q] = dd[136 + q];
        }
        const float* wp = &wsm[ic * 72];
        #pragma unroll
        for (int t = 0; t < 9; t++) {
            const int ky = t / 3, kx = t % 3;
            const ull* wq = reinterpret_cast<const ull*>(wp + t * 8);
            ull w0 = wq[0], w1q = wq[1], w2q = wq[2], w3q = wq[3];
            #pragma unroll
            for (int p = 0; p < 8; p++) {
                ull d = dup2(rw[ky][p + kx]);
                acc2[0][p] = ffma2(d, w0,  acc2[0][p]);
                acc2[1][p] = ffma2(d, w1q, acc2[1][p]);
                acc2[2][p] = ffma2(d, w2q, acc2[2][p]);
                acc2[3][p] = ffma2(d, w3q, acc2[3][p]);
            }
        }
    }

    const int gy  = tileY + ty;
    const int gx0 = tileX + tx;
    const float inv_sqrt2 = 0.70710678118654752f;
    float* hbase = g_h + ((size_t)b * NPIX + (size_t)gy * WW + gx0) * SHC;
    #pragma unroll
    for (int p = 0; p < 8; p++) {
        float v[8];
        unpack2(acc2[0][p], v[0], v[1]);
        unpack2(acc2[1][p], v[2], v[3]);
        unpack2(acc2[2][p], v[4], v[5]);
        unpack2(acc2[3][p], v[6], v[7]);
        float4 o0, o1;
        float u;
        u = v[0]; o0.x = 0.5f * u * (1.f + erff(u * inv_sqrt2));
        u = v[1]; o0.y = 0.5f * u * (1.f + erff(u * inv_sqrt2));
        u = v[2]; o0.z = 0.5f * u * (1.f + erff(u * inv_sqrt2));
        u = v[3]; o0.w = 0.5f * u * (1.f + erff(u * inv_sqrt2));
        u = v[4]; o1.x = 0.5f * u * (1.f + erff(u * inv_sqrt2));
        u = v[5]; o1.y = 0.5f * u * (1.f + erff(u * inv_sqrt2));
        u = v[6]; o1.z = 0.5f * u * (1.f + erff(u * inv_sqrt2));
        u = v[7]; o1.w = 0.5f * u * (1.f + erff(u * inv_sqrt2));
        float4* hp = reinterpret_cast<float4*>(hbase + (size_t)p * SHC);
        hp[0] = o0;
        hp[1] = o1;
    }
}

// ---------------------------------------------------------------------------
// Kernel 2: 2 blocks per (b,c); full padded image in smem; 576 threads,
// 2-pixel ILP per thread (rows y and y+48) to hide LDG/MUFU/LDS latency.
// ---------------------------------------------------------------------------
#define PAD 200

__global__ void __launch_bounds__(576, 1)
fuse_kernel(const float* __restrict__ x, const float* __restrict__ w2,
            const float* __restrict__ b2, const float* __restrict__ lsc,
            float* __restrict__ out)
{
    extern __shared__ float img[];           // NPIX + PAD floats
    const int bc   = blockIdx.x >> 1;
    const int half = blockIdx.x & 1;
    const int c    = bc & 63;

    const float4* src  = reinterpret_cast<const float4*>(x + (size_t)bc * NPIX);
    float4*       dst4 = reinterpret_cast<float4*>(img);
    #pragma unroll 4
    for (int i = threadIdx.x; i < NPIX / 4; i += 576) dst4[i] = src[i];
    if (threadIdx.x < PAD / 4)
        reinterpret_cast<float4*>(img + NPIX)[threadIdx.x] = make_float4(0.f, 0.f, 0.f, 0.f);

    // packed per-channel weights: w01[s]=(w_a,w_bx), w23[s]=(w_by,w_c)
    ull w01[8], w23[8];
    #pragma unroll
    for (int s = 0; s < 8; s++) {
        w01[s] = pack2(__ldg(&w2[(4 * c + 0) * 8 + s]), __ldg(&w2[(4 * c + 1) * 8 + s]));
        w23[s] = pack2(__ldg(&w2[(4 * c + 2) * 8 + s]), __ldg(&w2[(4 * c + 3) * 8 + s]));
    }
    const ull bias01 = pack2(__ldg(&b2[4 * c + 0]), __ldg(&b2[4 * c + 1]));
    const ull bias23 = pack2(__ldg(&b2[4 * c + 2]), __ldg(&b2[4 * c + 3]));

    const float esc = expf(__ldg(lsc));
    const float* hb = g_h + (size_t)(bc >> 6) * NPIX * SHC;
    float* ob = out + (size_t)bc * NPIX;

    const float step = 2.0f / 191.0f;

    const int rphase = threadIdx.x / 192;            // 0..2
    const int xi     = threadIdx.x - rphase * 192;   // 0..191
    const float gxv  = fmaf((float)xi, step, -1.0f);
    const int y0     = half * 96 + rphase;

    __syncthreads();

    #pragma unroll 1
    for (int k = 0; k < 16; k++) {
        const int yiA  = y0 + 3 * k;
        const int idxA = yiA * WW + xi;
        const int idxB = idxA + 48 * WW;

        int   idx[2] = { idxA, idxB };
        float gyv[2] = { fmaf((float)yiA,        step, -1.0f),
                         fmaf((float)(yiA + 48), step, -1.0f) };

        // ---- phase 1: both pixels' h loads (4x LDG.128 back-to-back) ----
        float4 h0[2], h1[2];
        #pragma unroll
        for (int j = 0; j < 2; j++) {
            const float4* hp = reinterpret_cast<const float4*>(hb + (size_t)idx[j] * SHC);
            h0[j] = hp[0];
            h1[j] = hp[1];
        }

        // ---- phase 2: coeff dot-products (packed), both pixels ----
        float s[2], dxv[2], dyv[2], cvv[2];
        #pragma unroll
        for (int j = 0; j < 2; j++) {
            ull a01 = bias01, a23 = bias23;
            ull d;
            d = dup2(h0[j].x); a01 = ffma2(d, w01[0], a01); a23 = ffma2(d, w23[0], a23);
            d = dup2(h0[j].y); a01 = ffma2(d, w01[1], a01); a23 = ffma2(d, w23[1], a23);
            d = dup2(h0[j].z); a01 = ffma2(d, w01[2], a01); a23 = ffma2(d, w23[2], a23);
            d = dup2(h0[j].w); a01 = ffma2(d, w01[3], a01); a23 = ffma2(d, w23[3], a23);
            d = dup2(h1[j].x); a01 = ffma2(d, w01[4], a01); a23 = ffma2(d, w23[4], a23);
            d = dup2(h1[j].y); a01 = ffma2(d, w01[5], a01); a23 = ffma2(d, w23[5], a23);
            d = dup2(h1[j].z); a01 = ffma2(d, w01[6], a01); a23 = ffma2(d, w23[6], a23);
            d = dup2(h1[j].w); a01 = ffma2(d, w01[7], a01); a23 = ffma2(d, w23[7], a23);
            float a, bx, by, cv;
            unpack2(a01, a, bx);
            unpack2(a23, by, cv);

            // softplus (stable) + sqrt, MUFU path
            float t  = __expf(-fabsf(a));
            float sp = fmaxf(a, 0.f) + __logf(1.0f + t);
            s[j]   = fsqrt_approx(fmaf(sp, 0.1f, 1e-8f));
            dxv[j] = bx * 0.1f;
            dyv[j] = by * 0.1f;
            cvv[j] = fminf(fmaxf(cv, -5.f), 5.f);
        }

        // ---- phase 3: bilinear taps + store, both pixels ----
        #pragma unroll
        for (int j = 0; j < 2; j++) {
            float px1  = fmaf((gxv + s[j]) + dxv[j], 95.5f, 95.5f);
            float px2  = fmaf((gxv - s[j]) + dxv[j], 95.5f, 95.5f);
            float px3  = fmaf( gxv + dxv[j],         95.5f, 95.5f);
            float py12 = fmaf( gyv[j] + dyv[j],          95.5f, 95.5f);
            float py3  = fmaf((gyv[j] + s[j]) + dyv[j],  95.5f, 95.5f);
            float py4  = fmaf((gyv[j] - s[j]) + dyv[j],  95.5f, 95.5f);

            float pyc = fminf(fmaxf(py12, 0.f), 191.f);
            float y0f = floorf(pyc);
            float wy  = pyc - y0f;

            float pxc1 = fminf(fmaxf(px1, 0.f), 191.f);
            float x0f1 = floorf(pxc1);
            float wx1  = pxc1 - x0f1;
            int   o1   = (int)fmaf(y0f, 192.f, x0f1);
            float v00 = img[o1],       v01 = img[o1 + 1];
            float v10 = img[o1 + 192], v11 = img[o1 + 193];
            float top = fmaf(v01 - v00, wx1, v00);
            float bot = fmaf(v11 - v10, wx1, v10);
            float u1  = fmaf(bot - top, wy, top);

            float pxc2 = fminf(fmaxf(px2, 0.f), 191.f);
            float x0f2 = floorf(pxc2);
            float wx2  = pxc2 - x0f2;
            int   o2   = (int)fmaf(y0f, 192.f, x0f2);
            v00 = img[o2];       v01 = img[o2 + 1];
            v10 = img[o2 + 192]; v11 = img[o2 + 193];
            top = fmaf(v01 - v00, wx2, v00);
            bot = fmaf(v11 - v10, wx2, v10);
            float u2 = fmaf(bot - top, wy, top);

            float pxc3 = fminf(fmaxf(px3, 0.f), 191.f);
            float x0f3 = floorf(pxc3);
            float wx3  = pxc3 - x0f3;

            float pyc3 = fminf(fmaxf(py3, 0.f), 191.f);
            float y0f3 = floorf(pyc3);
            float wy3  = pyc3 - y0f3;
            int   o3   = (int)fmaf(y0f3, 192.f, x0f3);
            v00 = img[o3];       v01 = img[o3 + 1];
            v10 = img[o3 + 192]; v11 = img[o3 + 193];
            top = fmaf(v01 - v00, wx3, v00);
            bot = fmaf(v11 - v10, wx3, v10);
            float u3 = fmaf(bot - top, wy3, top);

            float pyc4 = fminf(fmaxf(py4, 0.f), 191.f);
            float y0f4 = floorf(pyc4);
            float wy4  = pyc4 - y0f4;
            int   o4   = (int)fmaf(y0f4, 192.f, x0f3);
            v00 = img[o4];       v01 = img[o4 + 1];
            v10 = img[o4 + 192]; v11 = img[o4 + 193];
            top = fmaf(v01 - v00, wx3, v00);
            bot = fmaf(v11 - v10, wx3, v10);
            float u4 = fmaf(bot - top, wy4, top);

            float evo = 0.25f * (((u1 + u2) + u3) + u4);
            float xv  = img[idx[j]];
            ob[idx[j]] = esc * (evo + (0.1f * cvv[j]) * xv);
        }
    }
}

// ---------------------------------------------------------------------------
extern "C" void kernel_launch(void* const* d_in, const int* in_sizes, int n_in,
                              void* d_out, int out_size)
{
    const float *x = nullptr, *w1 = nullptr, *w2 = nullptr, *b2 = nullptr, *ls = nullptr;
    for (int i = 0; i < n_in; i++) {
        switch (in_sizes[i]) {
            case NB * CIN * NPIX: x  = (const float*)d_in[i]; break;  // 18874368
            case SHC * CIN * 9:   w1 = (const float*)d_in[i]; break;  // 4608
            case 4 * CIN * SHC:   w2 = (const float*)d_in[i]; break;  // 2048
            case 4 * CIN:         b2 = (const float*)d_in[i]; break;  // 256
            case 1:               ls = (const float*)d_in[i]; break;
            default: break;
        }
    }

    dim3 g1(3, 6, NB);                       // 64x32 tiles
    conv1_gelu_kernel<<<g1, 256>>>(x, w1);

    const int smem = (NPIX + PAD) * (int)sizeof(float);  // 148256
    cudaFuncSetAttribute(fuse_kernel, cudaFuncAttributeMaxDynamicSharedMemorySize, smem);
    fuse_kernel<<<NB * CIN * 2, 576, smem>>>(x, w2, b2, ls, (float*)d_out);
}

// round 5
// speedup vs baseline: 1.4396x; 1.0017x over previous
#include <cuda_runtime.h>
#include <math.h>

#define HH   192
#define WW   192
#define CIN  64
#define SHC  8
#define NB   8
#define NPIX (HH*WW)

typedef unsigned long long ull;

// scratch for h = gelu(conv1(x)), PIXEL-MAJOR: [b][pix][8 sh-channels] (9.4 MB)
__device__ float g_h[(size_t)NB * NPIX * SHC];

__device__ __forceinline__ void cp_async4(void* dst, const void* src) {
    unsigned s = (unsigned)__cvta_generic_to_shared(dst);
    asm volatile("cp.async.ca.shared.global [%0], [%1], 4;\n" :: "r"(s), "l"(src));
}
__device__ __forceinline__ float fsqrt_approx(float v) {
    float r; asm("sqrt.approx.f32 %0, %1;" : "=f"(r) : "f"(v)); return r;
}
// ---- f32x2 packed helpers ----
__device__ __forceinline__ ull ffma2(ull a, ull b, ull c) {
    ull r; asm("fma.rn.f32x2 %0, %1, %2, %3;" : "=l"(r) : "l"(a), "l"(b), "l"(c)); return r;
}
__device__ __forceinline__ ull dup2(float v) {
    ull r; asm("mov.b64 %0, {%1, %1};" : "=l"(r) : "f"(v)); return r;
}
__device__ __forceinline__ ull pack2(float lo, float hi) {
    ull r; asm("mov.b64 %0, {%1, %2};" : "=l"(r) : "f"(lo), "f"(hi)); return r;
}
__device__ __forceinline__ void unpack2(ull v, float& lo, float& hi) {
    asm("mov.b64 {%0, %1}, %2;" : "=f"(lo), "=f"(hi) : "l"(v));
}

// ---------------------------------------------------------------------------
// Kernel 1: 3x3 SAME conv (64 -> 8) + exact GELU  (at scalar issue floor).
// ---------------------------------------------------------------------------
__global__ void __launch_bounds__(256, 1)
conv1_gelu_kernel(const float* __restrict__ x, const float* __restrict__ w1)
{
    __shared__ float wsm[CIN * 9 * SHC];
    __shared__ float dsm[2][34 * 68];

    const int tid   = threadIdx.x;
    const int b     = blockIdx.z;
    const int tileX = blockIdx.x * 64;
    const int tileY = blockIdx.y * 32;

    for (int i = tid; i < CIN * 9 * SHC; i += 256) {
        int oc  = i & 7;
        int tap = (i >> 3) % 9;
        int ic  = i / 72;
        wsm[i] = w1[(oc * CIN + ic) * 9 + tap];
    }

    const float* xb = x + (size_t)b * CIN * NPIX;

    auto load_tile = [&](int ic, int buf) {
        const float* src = xb + (size_t)ic * NPIX;
        for (int i = tid; i < 34 * 66; i += 256) {
            int r    = i / 66;
            int ccol = i - r * 66;
            int gy   = tileY - 1 + r;
            int gx   = tileX - 1 + ccol;
            float* dp = &dsm[buf][r * 68 + ccol];
            if ((unsigned)gy < (unsigned)HH && (unsigned)gx < (unsigned)WW)
                cp_async4(dp, src + gy * WW + gx);
            else
                *dp = 0.f;
        }
    };

    load_tile(0, 0);
    asm volatile("cp.async.commit_group;\n");

    const int tx = (tid & 7) * 8;
    const int ty = tid >> 3;

    ull acc2[4][8];
    #pragma unroll
    for (int q = 0; q < 4; q++)
        #pragma unroll
        for (int p = 0; p < 8; p++) acc2[q][p] = 0ull;

    for (int ic = 0; ic < CIN; ic++) {
        __syncthreads();
        if (ic + 1 < CIN) {
            load_tile(ic + 1, (ic + 1) & 1);
            asm volatile("cp.async.commit_group;\n");
            asm volatile("cp.async.wait_group 1;\n");
        } else {
            asm volatile("cp.async.wait_group 0;\n");
        }
        __syncthreads();

        const float* dd = &dsm[ic & 1][ty * 68 + tx];
        float rw[3][10];
        #pragma unroll
        for (int q = 0; q < 10; q++) {
            rw[0][q] = dd[q];
            rw[1][q] = dd[68 + q];
            rw[2][q] = dd[136 + q];
        }
        const float* wp = &wsm[ic * 72];
        #pragma unroll
        for (int t = 0; t < 9; t++) {
            const int ky = t / 3, kx = t % 3;
            const ull* wq = reinterpret_cast<const ull*>(wp + t * 8);
            ull w0 = wq[0], w1q = wq[1], w2q = wq[2], w3q = wq[3];
            #pragma unroll
            for (int p = 0; p < 8; p++) {
                ull d = dup2(rw[ky][p + kx]);
                acc2[0][p] = ffma2(d, w0,  acc2[0][p]);
                acc2[1][p] = ffma2(d, w1q, acc2[1][p]);
                acc2[2][p] = ffma2(d, w2q, acc2[2][p]);
                acc2[3][p] = ffma2(d, w3q, acc2[3][p]);
            }
        }
    }

    const int gy  = tileY + ty;
    const int gx0 = tileX + tx;
    const float inv_sqrt2 = 0.70710678118654752f;
    float* hbase = g_h + ((size_t)b * NPIX + (size_t)gy * WW + gx0) * SHC;
    #pragma unroll
    for (int p = 0; p < 8; p++) {
        float v[8];
        unpack2(acc2[0][p], v[0], v[1]);
        unpack2(acc2[1][p], v[2], v[3]);
        unpack2(acc2[2][p], v[4], v[5]);
        unpack2(acc2[3][p], v[6], v[7]);
        float4 o0, o1;
        float u;
        u = v[0]; o0.x = 0.5f * u * (1.f + erff(u * inv_sqrt2));
        u = v[1]; o0.y = 0.5f * u * (1.f + erff(u * inv_sqrt2));
        u = v[2]; o0.z = 0.5f * u * (1.f + erff(u * inv_sqrt2));
        u = v[3]; o0.w = 0.5f * u * (1.f + erff(u * inv_sqrt2));
        u = v[4]; o1.x = 0.5f * u * (1.f + erff(u * inv_sqrt2));
        u = v[5]; o1.y = 0.5f * u * (1.f + erff(u * inv_sqrt2));
        u = v[6]; o1.z = 0.5f * u * (1.f + erff(u * inv_sqrt2));
        u = v[7]; o1.w = 0.5f * u * (1.f + erff(u * inv_sqrt2));
        float4* hp = reinterpret_cast<float4*>(hbase + (size_t)p * SHC);
        hp[0] = o0;
        hp[1] = o1;
    }
}

// ---------------------------------------------------------------------------
// Kernel 2: constant-folded pixel-space version. 2 blocks per (b,c), full
// padded image in smem, 576 threads, 2-pixel ILP (rows y, y+48).
// Weights pre-scaled so the dot product emits pixel-space dx,dy and
// sqrt-argument directly; base grid in pixel units; esc folded into epilogue.
// ---------------------------------------------------------------------------
#define PAD 200

__global__ void __launch_bounds__(576, 1)
fuse_kernel(const float* __restrict__ x, const float* __restrict__ w2,
            const float* __restrict__ b2, const float* __restrict__ lsc,
            float* __restrict__ out)
{
    extern __shared__ float img[];           // NPIX + PAD floats
    const int bc   = blockIdx.x >> 1;
    const int half = blockIdx.x & 1;
    const int c    = bc & 63;

    const float4* src  = reinterpret_cast<const float4*>(x + (size_t)bc * NPIX);
    float4*       dst4 = reinterpret_cast<float4*>(img);
    #pragma unroll 4
    for (int i = threadIdx.x; i < NPIX / 4; i += 576) dst4[i] = src[i];
    if (threadIdx.x < PAD / 4)
        reinterpret_cast<float4*>(img + NPIX)[threadIdx.x] = make_float4(0.f, 0.f, 0.f, 0.f);

    // pre-scaled packed weights:
    //   lane pair (a, bx') where bx' = bx * 9.55  (0.1 shift * 95.5 px-scale)
    //   lane pair (by', c) where by' = by * 9.55
    const float PXS = 9.55f;                 // 0.1 * 95.5
    ull w01[8], w23[8];
    #pragma unroll
    for (int s = 0; s < 8; s++) {
        w01[s] = pack2(__ldg(&w2[(4 * c + 0) * 8 + s]),
                       __ldg(&w2[(4 * c + 1) * 8 + s]) * PXS);
        w23[s] = pack2(__ldg(&w2[(4 * c + 2) * 8 + s]) * PXS,
                       __ldg(&w2[(4 * c + 3) * 8 + s]));
    }
    const ull bias01 = pack2(__ldg(&b2[4 * c + 0]), __ldg(&b2[4 * c + 1]) * PXS);
    const ull bias23 = pack2(__ldg(&b2[4 * c + 2]) * PXS, __ldg(&b2[4 * c + 3]));

    const float esc   = expf(__ldg(lsc));
    const float esc4  = 0.25f * esc;
    const float esc01 = 0.1f  * esc;
    const float* hb = g_h + (size_t)(bc >> 6) * NPIX * SHC;
    float* ob = out + (size_t)bc * NPIX;

    const float step = 2.0f / 191.0f;

    const int rphase = threadIdx.x / 192;            // 0..2
    const int xi     = threadIdx.x - rphase * 192;   // 0..191
    // base grid in pixel units, hoisted (ref rounding for the base term)
    const float gxpix = (fmaf((float)xi, step, -1.0f) + 1.0f) * 95.5f;
    const int y0     = half * 96 + rphase;

    // prefetch first iteration's h before the staging barrier
    const int idxA0 = y0 * WW + xi;
    float4 ph0A = reinterpret_cast<const float4*>(hb + (size_t)idxA0 * SHC)[0];
    float4 ph1A = reinterpret_cast<const float4*>(hb + (size_t)idxA0 * SHC)[1];
    float4 ph0B = reinterpret_cast<const float4*>(hb + (size_t)(idxA0 + 48 * WW) * SHC)[0];
    float4 ph1B = reinterpret_cast<const float4*>(hb + (size_t)(idxA0 + 48 * WW) * SHC)[1];

    __syncthreads();

    #pragma unroll 1
    for (int k = 0; k < 16; k++) {
        const int yiA  = y0 + 3 * k;
        const int idxA = yiA * WW + xi;

        int   idx[2]   = { idxA, idxA + 48 * WW };
        float gypix[2] = { (fmaf((float)yiA,        step, -1.0f) + 1.0f) * 95.5f,
                           (fmaf((float)(yiA + 48), step, -1.0f) + 1.0f) * 95.5f };

        float4 h0[2], h1[2];
        h0[0] = ph0A; h1[0] = ph1A;
        h0[1] = ph0B; h1[1] = ph1B;
        if (k < 15) {    // prefetch next iteration
            const int nIdx = idxA + 3 * WW;
            ph0A = reinterpret_cast<const float4*>(hb + (size_t)nIdx * SHC)[0];
            ph1A = reinterpret_cast<const float4*>(hb + (size_t)nIdx * SHC)[1];
            ph0B = reinterpret_cast<const float4*>(hb + (size_t)(nIdx + 48 * WW) * SHC)[0];
            ph1B = reinterpret_cast<const float4*>(hb + (size_t)(nIdx + 48 * WW) * SHC)[1];
        }

        float s95[2], dxp[2], dyp[2], cvv[2];
        #pragma unroll
        for (int j = 0; j < 2; j++) {
            ull a01 = bias01, a23 = bias23;
            ull d;
            d = dup2(h0[j].x); a01 = ffma2(d, w01[0], a01); a23 = ffma2(d, w23[0], a23);
            d = dup2(h0[j].y); a01 = ffma2(d, w01[1], a01); a23 = ffma2(d, w23[1], a23);
            d = dup2(h0[j].z); a01 = ffma2(d, w01[2], a01); a23 = ffma2(d, w23[2], a23);
            d = dup2(h0[j].w); a01 = ffma2(d, w01[3], a01); a23 = ffma2(d, w23[3], a23);
            d = dup2(h1[j].x); a01 = ffma2(d, w01[4], a01); a23 = ffma2(d, w23[4], a23);
            d = dup2(h1[j].y); a01 = ffma2(d, w01[5], a01); a23 = ffma2(d, w23[5], a23);
            d = dup2(h1[j].z); a01 = ffma2(d, w01[6], a01); a23 = ffma2(d, w23[6], a23);
            d = dup2(h1[j].w); a01 = ffma2(d, w01[7], a01); a23 = ffma2(d, w23[7], a23);
            float a, bxp, byp, cv;
            unpack2(a01, a, bxp);
            unpack2(a23, byp, cv);

            // softplus, then sqrt with 95.5^2*0.1 folded in:
            // s95 = 95.5*sqrt(sp*0.1+1e-8) = sqrt(sp*912.025 + 9.12025e-5)
            float t  = __expf(-fabsf(a));
            float sp = fmaxf(a, 0.f) + __logf(1.0f + t);
            s95[j] = fsqrt_approx(fmaf(sp, 912.025f, 9.12025e-5f));
            dxp[j] = bxp;                                  // already pixel units
            dyp[j] = byp;
            cvv[j] = fminf(fmaxf(cv, -5.f), 5.f);
        }

        #pragma unroll
        for (int j = 0; j < 2; j++) {
            float px3  = gxpix    + dxp[j];
            float px1  = px3      + s95[j];
            float px2  = px3      - s95[j];
            float py12 = gypix[j] + dyp[j];
            float py3  = py12     + s95[j];
            float py4  = py12     - s95[j];

            float pyc = fminf(fmaxf(py12, 0.f), 191.f);
            float y0f = floorf(pyc);
            float wy  = pyc - y0f;

            float pxc1 = fminf(fmaxf(px1, 0.f), 191.f);
            float x0f1 = floorf(pxc1);
            float wx1  = pxc1 - x0f1;
            int   o1   = (int)fmaf(y0f, 192.f, x0f1);
            float v00 = img[o1],       v01 = img[o1 + 1];
            float v10 = img[o1 + 192], v11 = img[o1 + 193];
            float top = fmaf(v01 - v00, wx1, v00);
            float bot = fmaf(v11 - v10, wx1, v10);
            float u1  = fmaf(bot - top, wy, top);

            float pxc2 = fminf(fmaxf(px2, 0.f), 191.f);
            float x0f2 = floorf(pxc2);
            float wx2  = pxc2 - x0f2;
            int   o2   = (int)fmaf(y0f, 192.f, x0f2);
            v00 = img[o2];       v01 = img[o2 + 1];
            v10 = img[o2 + 192]; v11 = img[o2 + 193];
            top = fmaf(v01 - v00, wx2, v00);
            bot = fmaf(v11 - v10, wx2, v10);
            float u2 = fmaf(bot - top, wy, top);

            float pxc3 = fminf(fmaxf(px3, 0.f), 191.f);
            float x0f3 = floorf(pxc3);
            float wx3  = pxc3 - x0f3;

            float pyc3 = fminf(fmaxf(py3, 0.f), 191.f);
            float y0f3 = floorf(pyc3);
            float wy3  = pyc3 - y0f3;
            int   o3   = (int)fmaf(y0f3, 192.f, x0f3);
            v00 = img[o3];       v01 = img[o3 + 1];
            v10 = img[o3 + 192]; v11 = img[o3 + 193];
            top = fmaf(v01 - v00, wx3, v00);
            bot = fmaf(v11 - v10, wx3, v10);
            float u3 = fmaf(bot - top, wy3, top);

            float pyc4 = fminf(fmaxf(py4, 0.f), 191.f);
            float y0f4 = floorf(pyc4);
            float wy4  = pyc4 - y0f4;
            int   o4   = (int)fmaf(y0f4, 192.f, x0f3);
            v00 = img[o4];       v01 = img[o4 + 1];
            v10 = img[o4 + 192]; v11 = img[o4 + 193];
            top = fmaf(v01 - v00, wx3, v00);
            bot = fmaf(v11 - v10, wx3, v10);
            float u4 = fmaf(bot - top, wy4, top);

            float usum = (u1 + u2) + (u3 + u4);
            float xv   = img[idx[j]];
            ob[idx[j]] = fmaf(esc4, usum, esc01 * cvv[j] * xv);
        }
    }
}

// ---------------------------------------------------------------------------
extern "C" void kernel_launch(void* const* d_in, const int* in_sizes, int n_in,
                              void* d_out, int out_size)
{
    const float *x = nullptr, *w1 = nullptr, *w2 = nullptr, *b2 = nullptr, *ls = nullptr;
    for (int i = 0; i < n_in; i++) {
        switch (in_sizes[i]) {
            case NB * CIN * NPIX: x  = (const float*)d_in[i]; break;
            case SHC * CIN * 9:   w1 = (const float*)d_in[i]; break;
            case 4 * CIN * SHC:   w2 = (const float*)d_in[i]; break;
            case 4 * CIN:         b2 = (const float*)d_in[i]; break;
            case 1:               ls = (const float*)d_in[i]; break;
            default: break;
        }
    }

    dim3 g1(3, 6, NB);
    conv1_gelu_kernel<<<g1, 256>>>(x, w1);

    const int smem = (NPIX + PAD) * (int)sizeof(float);
    cudaFuncSetAttribute(fuse_kernel, cudaFuncAttributeMaxDynamicSharedMemorySize, smem);
    fuse_kernel<<<NB * CIN * 2, 576, smem>>>(x, w2, b2, ls, (float*)d_out);
}